// round 5
// baseline (speedup 1.0000x reference)
#include <cuda_runtime.h>

#define N_NODES 100000
#define N_EDGES 1000000
#define IN_DIM  37
#define HID     64
#define BN_EPS  1e-5f

// -------- scratch (device globals; no allocation allowed) --------
__device__ float g_hs [N_NODES * HID];   // dinv-scaled GEMM output
__device__ float g_acc[N_NODES * HID];   // edge aggregation accumulator
__device__ float g_x0 [N_NODES * HID];   // layer-1 output
__device__ float g_x1 [N_NODES * HID];   // layer-2 output
__device__ int   g_deg [N_NODES];
__device__ float g_dinv[N_NODES];
__device__ int   g_is64;

// -------- edge_index dtype detection (int64 vs int32) --------
__global__ void detect_dtype(const unsigned* __restrict__ ei_raw) {
    if (blockIdx.x == 0 && threadIdx.x == 0) {
        int ok = 1;
        #pragma unroll 1
        for (int i = 0; i < 64; i++)
            if (ei_raw[2 * i + 1] != 0u) ok = 0;
        g_is64 = ok;  // all high words zero -> int64 layout
    }
}

__device__ __forceinline__ int edge_at(const void* ei, long long idx, int is64) {
    if (is64) return (int)((const long long*)ei)[idx];
    return ((const int*)ei)[idx];
}

// -------- degree / dinv --------
__global__ void deg_init() {
    int v = blockIdx.x * blockDim.x + threadIdx.x;
    if (v < N_NODES) g_deg[v] = 1;  // self loop
}

__global__ void deg_count(const void* __restrict__ ei) {
    int e = blockIdx.x * blockDim.x + threadIdx.x;
    if (e < N_EDGES) {
        int is64 = g_is64;
        int col = edge_at(ei, (long long)N_EDGES + e, is64);
        atomicAdd(&g_deg[col], 1);
    }
}

__global__ void dinv_kernel() {
    int v = blockIdx.x * blockDim.x + threadIdx.x;
    if (v < N_NODES) g_dinv[v] = rsqrtf((float)g_deg[v]);
}

// -------- GEMM: hs[v,:] = dinv[v] * (x[v,:] @ W); also zeroes g_acc[v,:] --------
// sel: 0 -> xext (harness input), 1 -> g_x0, 2 -> g_x1
template <int K>
__global__ void gemm_scale(const float* __restrict__ xext, int sel,
                           const float* __restrict__ W) {
    __shared__ __align__(16) float Wsh[K * HID];
    for (int i = threadIdx.x; i < K * HID; i += blockDim.x) Wsh[i] = W[i];
    __syncthreads();

    int v = blockIdx.x * blockDim.x + threadIdx.x;
    if (v >= N_NODES) return;

    const float* x = (sel == 0) ? xext : (sel == 1 ? g_x0 : g_x1);

    float4 acc[16];
    #pragma unroll
    for (int j = 0; j < 16; j++) acc[j] = make_float4(0.f, 0.f, 0.f, 0.f);

    const float* xr = x + (long long)v * K;
    #pragma unroll 4
    for (int k = 0; k < K; k++) {
        float xv = xr[k];
        const float4* wr = (const float4*)(Wsh + k * HID);
        #pragma unroll
        for (int j = 0; j < 16; j++) {
            float4 w = wr[j];
            acc[j].x += xv * w.x;
            acc[j].y += xv * w.y;
            acc[j].z += xv * w.z;
            acc[j].w += xv * w.w;
        }
    }

    float d = g_dinv[v];
    float4* out = (float4*)(g_hs  + (long long)v * HID);
    float4* ac  = (float4*)(g_acc + (long long)v * HID);
    float4 z = make_float4(0.f, 0.f, 0.f, 0.f);
    #pragma unroll
    for (int j = 0; j < 16; j++) {
        float4 a = acc[j];
        a.x *= d; a.y *= d; a.z *= d; a.w *= d;
        out[j] = a;
        ac[j]  = z;
    }
}

// -------- scatter: acc[col,:] += hs[row,:] (dinv[col] deferred to epilogue) --------
__global__ void scatter_edges(const void* __restrict__ ei) {
    long long t = (long long)blockIdx.x * blockDim.x + threadIdx.x;
    if (t >= (long long)N_EDGES * 16) return;
    int e = (int)(t >> 4);
    int c = (int)(t & 15);
    int is64 = g_is64;
    int row = edge_at(ei, e, is64);
    int col = edge_at(ei, (long long)N_EDGES + e, is64);
    const float4 v = *(const float4*)(g_hs + (long long)row * HID + c * 4);
    float* dst = g_acc + (long long)col * HID + c * 4;
    asm volatile("red.global.add.v4.f32 [%0], {%1, %2, %3, %4};"
                 :: "l"(dst), "f"(v.x), "f"(v.y), "f"(v.z), "f"(v.w)
                 : "memory");
}

// -------- epilogue: out = relu(BN(dinv*(acc+hs) + b)) (+ residual) --------
// osel: 0 -> g_x0, 1 -> g_x1, 2 -> dout ; rsel: -1 none, 0 g_x0, 1 g_x1
__global__ void epilogue(int osel, int rsel, float* __restrict__ dout,
                         const float* __restrict__ b,
                         const float* __restrict__ gamma,
                         const float* __restrict__ beta,
                         const float* __restrict__ mean,
                         const float* __restrict__ var) {
    long long t = (long long)blockIdx.x * blockDim.x + threadIdx.x;
    if (t >= (long long)N_NODES * 16) return;
    int v = (int)(t >> 4);
    int j = (int)(t & 15) * 4;

    float d = g_dinv[v];
    const float4 a  = *(const float4*)(g_acc + (long long)v * HID + j);
    const float4 s  = *(const float4*)(g_hs  + (long long)v * HID + j);
    const float4 bb = *(const float4*)(b     + j);
    const float4 gg = *(const float4*)(gamma + j);
    const float4 be = *(const float4*)(beta  + j);
    const float4 mm = *(const float4*)(mean  + j);
    const float4 vv = *(const float4*)(var   + j);

    float4 o;
    o.x = fmaxf((d * (a.x + s.x) + bb.x - mm.x) * gg.x * rsqrtf(vv.x + BN_EPS) + be.x, 0.f);
    o.y = fmaxf((d * (a.y + s.y) + bb.y - mm.y) * gg.y * rsqrtf(vv.y + BN_EPS) + be.y, 0.f);
    o.z = fmaxf((d * (a.z + s.z) + bb.z - mm.z) * gg.z * rsqrtf(vv.z + BN_EPS) + be.z, 0.f);
    o.w = fmaxf((d * (a.w + s.w) + bb.w - mm.w) * gg.w * rsqrtf(vv.w + BN_EPS) + be.w, 0.f);

    if (rsel >= 0) {
        const float* r = (rsel == 0) ? g_x0 : g_x1;
        const float4 rv = *(const float4*)(r + (long long)v * HID + j);
        o.x += rv.x; o.y += rv.y; o.z += rv.z; o.w += rv.w;
    }

    float* outp = (osel == 0) ? g_x0 : (osel == 1 ? g_x1 : dout);
    *(float4*)(outp + (long long)v * HID + j) = o;
}

// -------- launch --------
extern "C" void kernel_launch(void* const* d_in, const int* in_sizes, int n_in,
                              void* d_out, int out_size) {
    const float* x     = (const float*)d_in[0];
    const void*  ei    = d_in[1];
    const float* W1    = (const float*)d_in[2];
    const float* W2    = (const float*)d_in[3];
    const float* W3    = (const float*)d_in[4];
    const float* b     = (const float*)d_in[5];
    const float* gamma = (const float*)d_in[6];
    const float* beta  = (const float*)d_in[7];
    const float* mean  = (const float*)d_in[8];
    const float* var   = (const float*)d_in[9];
    float* out = (float*)d_out;

    const int T = 256;
    const int gN  = (N_NODES + T - 1) / T;
    const int gE  = (N_EDGES + T - 1) / T;
    const int gS  = (int)(((long long)N_EDGES * 16 + T - 1) / T);
    const int gEp = (int)(((long long)N_NODES * 16 + T - 1) / T);

    detect_dtype<<<1, 32>>>((const unsigned*)ei);
    deg_init<<<gN, T>>>();
    deg_count<<<gE, T>>>(ei);
    dinv_kernel<<<gN, T>>>();

    // layer 1: x(37) -> x0, no residual
    gemm_scale<IN_DIM><<<gN, T>>>(x, 0, W1);
    scatter_edges<<<gS, T>>>(ei);
    epilogue<<<gEp, T>>>(0, -1, out, b, gamma, beta, mean, var);

    // layer 2: x0 -> x1, residual x0
    gemm_scale<HID><<<gN, T>>>(nullptr, 1, W2);
    scatter_edges<<<gS, T>>>(ei);
    epilogue<<<gEp, T>>>(1, 0, out, b + HID, gamma + HID, beta + HID,
                         mean + HID, var + HID);

    // layer 3: x1 -> d_out, residual x1
    gemm_scale<HID><<<gN, T>>>(nullptr, 2, W3);
    scatter_edges<<<gS, T>>>(ei);
    epilogue<<<gEp, T>>>(2, 1, out, b + 2 * HID, gamma + 2 * HID, beta + 2 * HID,
                         mean + 2 * HID, var + 2 * HID);
}

// round 6
// speedup vs baseline: 1.3842x; 1.3842x over previous
#include <cuda_runtime.h>

#define N_NODES 100000
#define N_EDGES 1000000
#define IN_DIM  37
#define HID     64
#define BN_EPS  1e-5f

#define SCAN_B   1024
#define N_SBLK   ((N_NODES + SCAN_B - 1) / SCAN_B)   // 98

// -------- scratch (device globals; no allocation allowed) --------
__device__ float g_hs [N_NODES * HID];   // dinv-scaled GEMM output
__device__ float g_x0 [N_NODES * HID];   // layer-1 output
__device__ float g_x1 [N_NODES * HID];   // layer-2 output
__device__ int   g_deg   [N_NODES];      // real in-degree (no self loop)
__device__ float g_dinv  [N_NODES];
__device__ int   g_part  [N_NODES];      // per-block exclusive scan partials
__device__ int   g_bsum  [N_SBLK];
__device__ int   g_boff  [N_SBLK];
__device__ int   g_start [N_NODES];      // CSR row offsets (by col/target)
__device__ int   g_cursor[N_NODES];
__device__ int   g_csr   [N_EDGES];      // source node per CSR slot
__device__ int   g_is64;

// -------- edge_index dtype detection (int64 vs int32) --------
__global__ void detect_dtype(const unsigned* __restrict__ ei_raw) {
    if (blockIdx.x == 0 && threadIdx.x == 0) {
        int ok = 1;
        #pragma unroll 1
        for (int i = 0; i < 64; i++)
            if (ei_raw[2 * i + 1] != 0u) ok = 0;
        g_is64 = ok;  // all high words zero -> int64 layout
    }
}

__device__ __forceinline__ int edge_at(const void* ei, long long idx, int is64) {
    if (is64) return (int)((const long long*)ei)[idx];
    return ((const int*)ei)[idx];
}

// -------- degree --------
__global__ void deg_zero() {
    int v = blockIdx.x * blockDim.x + threadIdx.x;
    if (v < N_NODES) g_deg[v] = 0;
}

__global__ void deg_count(const void* __restrict__ ei) {
    int e = blockIdx.x * blockDim.x + threadIdx.x;
    if (e < N_EDGES) {
        int is64 = g_is64;
        int col = edge_at(ei, (long long)N_EDGES + e, is64);
        atomicAdd(&g_deg[col], 1);
    }
}

// -------- exclusive scan of g_deg (3 kernels) --------
__global__ void scan1() {
    __shared__ int s[SCAN_B];
    int t = threadIdx.x;
    int g = blockIdx.x * SCAN_B + t;
    int v = (g < N_NODES) ? g_deg[g] : 0;
    s[t] = v;
    __syncthreads();
    #pragma unroll
    for (int off = 1; off < SCAN_B; off <<= 1) {
        int x = (t >= off) ? s[t - off] : 0;
        __syncthreads();
        s[t] += x;
        __syncthreads();
    }
    int incl = s[t];
    if (g < N_NODES) g_part[g] = incl - v;      // exclusive within block
    if (t == SCAN_B - 1) g_bsum[blockIdx.x] = incl;
}

__global__ void scan2() {
    __shared__ int s[128];
    int t = threadIdx.x;
    int v = (t < N_SBLK) ? g_bsum[t] : 0;
    s[t] = v;
    __syncthreads();
    #pragma unroll
    for (int off = 1; off < 128; off <<= 1) {
        int x = (t >= off) ? s[t - off] : 0;
        __syncthreads();
        s[t] += x;
        __syncthreads();
    }
    if (t < N_SBLK) g_boff[t] = s[t] - v;       // exclusive block offsets
}

__global__ void scan3() {   // finalize offsets, init cursors, compute dinv
    int v = blockIdx.x * blockDim.x + threadIdx.x;
    if (v < N_NODES) {
        int st = g_part[v] + g_boff[v >> 10];
        g_start[v]  = st;
        g_cursor[v] = st;
        g_dinv[v]   = rsqrtf((float)(g_deg[v] + 1));   // +1 self loop
    }
}

// -------- CSR fill --------
__global__ void csr_fill(const void* __restrict__ ei) {
    int e = blockIdx.x * blockDim.x + threadIdx.x;
    if (e < N_EDGES) {
        int is64 = g_is64;
        int row = edge_at(ei, e, is64);
        int col = edge_at(ei, (long long)N_EDGES + e, is64);
        int pos = atomicAdd(&g_cursor[col], 1);
        g_csr[pos] = row;
    }
}

// -------- GEMM: hs[v,:] = dinv[v] * (x[v,:] @ W) --------
// sel: 0 -> xext (harness input), 1 -> g_x0, 2 -> g_x1
template <int K>
__global__ void gemm_scale(const float* __restrict__ xext, int sel,
                           const float* __restrict__ W) {
    __shared__ __align__(16) float Wsh[K * HID];
    for (int i = threadIdx.x; i < K * HID; i += blockDim.x) Wsh[i] = W[i];
    __syncthreads();

    int v = blockIdx.x * blockDim.x + threadIdx.x;
    if (v >= N_NODES) return;

    const float* x = (sel == 0) ? xext : (sel == 1 ? g_x0 : g_x1);

    float4 acc[16];
    #pragma unroll
    for (int j = 0; j < 16; j++) acc[j] = make_float4(0.f, 0.f, 0.f, 0.f);

    const float* xr = x + v * K;
    #pragma unroll 4
    for (int k = 0; k < K; k++) {
        float xv = xr[k];
        const float4* wr = (const float4*)(Wsh + k * HID);
        #pragma unroll
        for (int j = 0; j < 16; j++) {
            float4 w = wr[j];
            acc[j].x += xv * w.x;
            acc[j].y += xv * w.y;
            acc[j].z += xv * w.z;
            acc[j].w += xv * w.w;
        }
    }

    float d = g_dinv[v];
    float4* out = (float4*)(g_hs + v * HID);
    #pragma unroll
    for (int j = 0; j < 16; j++) {
        float4 a = acc[j];
        a.x *= d; a.y *= d; a.z *= d; a.w *= d;
        out[j] = a;
    }
}

// -------- fused aggregate + epilogue --------
// 16 threads per node, each owns one float4 feature chunk.
// o = relu(BN(dinv[v]*(sum_{src in csr[v]} hs[src] + hs[v]) + b)) (+ residual)
// osel: 0 -> g_x0, 1 -> g_x1, 2 -> dout ; rsel: -1 none, 0 g_x0, 1 g_x1
__global__ void aggregate_ep(int osel, int rsel, float* __restrict__ dout,
                             const float* __restrict__ b,
                             const float* __restrict__ gamma,
                             const float* __restrict__ beta,
                             const float* __restrict__ mean,
                             const float* __restrict__ var) {
    int t = threadIdx.x;
    int v = blockIdx.x * 16 + (t >> 4);
    int c = t & 15;
    if (v >= N_NODES) return;

    int start = g_start[v];
    int deg   = g_deg[v];
    int j     = c << 2;

    const int* __restrict__ cs = g_csr + start;
    float4 acc = make_float4(0.f, 0.f, 0.f, 0.f);

    int src = (deg > 0) ? cs[0] : 0;
    for (int i = 0; i < deg; i++) {
        int nsrc = (i + 1 < deg) ? cs[i + 1] : 0;
        const float4 val = *(const float4*)(g_hs + (src << 6) + j);
        acc.x += val.x; acc.y += val.y; acc.z += val.z; acc.w += val.w;
        src = nsrc;
    }

    // self loop
    const float4 s = *(const float4*)(g_hs + (v << 6) + j);
    acc.x += s.x; acc.y += s.y; acc.z += s.z; acc.w += s.w;

    float d = g_dinv[v];
    const float4 bb = *(const float4*)(b     + j);
    const float4 gg = *(const float4*)(gamma + j);
    const float4 be = *(const float4*)(beta  + j);
    const float4 mm = *(const float4*)(mean  + j);
    const float4 vv = *(const float4*)(var   + j);

    float4 o;
    o.x = fmaxf((d * acc.x + bb.x - mm.x) * gg.x * rsqrtf(vv.x + BN_EPS) + be.x, 0.f);
    o.y = fmaxf((d * acc.y + bb.y - mm.y) * gg.y * rsqrtf(vv.y + BN_EPS) + be.y, 0.f);
    o.z = fmaxf((d * acc.z + bb.z - mm.z) * gg.z * rsqrtf(vv.z + BN_EPS) + be.z, 0.f);
    o.w = fmaxf((d * acc.w + bb.w - mm.w) * gg.w * rsqrtf(vv.w + BN_EPS) + be.w, 0.f);

    if (rsel >= 0) {
        const float* r = (rsel == 0) ? g_x0 : g_x1;
        const float4 rv = *(const float4*)(r + (v << 6) + j);
        o.x += rv.x; o.y += rv.y; o.z += rv.z; o.w += rv.w;
    }

    float* outp = (osel == 0) ? g_x0 : (osel == 1 ? g_x1 : dout);
    *(float4*)(outp + (v << 6) + j) = o;
}

// -------- launch --------
extern "C" void kernel_launch(void* const* d_in, const int* in_sizes, int n_in,
                              void* d_out, int out_size) {
    const float* x     = (const float*)d_in[0];
    const void*  ei    = d_in[1];
    const float* W1    = (const float*)d_in[2];
    const float* W2    = (const float*)d_in[3];
    const float* W3    = (const float*)d_in[4];
    const float* b     = (const float*)d_in[5];
    const float* gamma = (const float*)d_in[6];
    const float* beta  = (const float*)d_in[7];
    const float* mean  = (const float*)d_in[8];
    const float* var   = (const float*)d_in[9];
    float* out = (float*)d_out;

    const int T = 256;
    const int gN  = (N_NODES + T - 1) / T;
    const int gE  = (N_EDGES + T - 1) / T;
    const int gA  = (N_NODES + 15) / 16;   // aggregate: 16 nodes/block of 256

    // ---- preprocessing (reused by all 3 layers) ----
    detect_dtype<<<1, 32>>>((const unsigned*)ei);
    deg_zero<<<gN, T>>>();
    deg_count<<<gE, T>>>(ei);
    scan1<<<N_SBLK, SCAN_B>>>();
    scan2<<<1, 128>>>();
    scan3<<<gN, T>>>();
    csr_fill<<<gE, T>>>(ei);

    // layer 1: x(37) -> x0, no residual
    gemm_scale<IN_DIM><<<gN, T>>>(x, 0, W1);
    aggregate_ep<<<gA, T>>>(0, -1, out, b, gamma, beta, mean, var);

    // layer 2: x0 -> x1, residual x0
    gemm_scale<HID><<<gN, T>>>(nullptr, 1, W2);
    aggregate_ep<<<gA, T>>>(1, 0, out, b + HID, gamma + HID, beta + HID,
                            mean + HID, var + HID);

    // layer 3: x1 -> d_out, residual x1
    gemm_scale<HID><<<gN, T>>>(nullptr, 2, W3);
    aggregate_ep<<<gA, T>>>(2, 1, out, b + 2 * HID, gamma + 2 * HID, beta + 2 * HID,
                            mean + 2 * HID, var + 2 * HID);
}

// round 7
// speedup vs baseline: 1.4041x; 1.0144x over previous
#include <cuda_runtime.h>
#include <cuda_fp16.h>

#define N_NODES 100000
#define N_EDGES 1000000
#define IN_DIM  37
#define HID     64
#define BN_EPS  1e-5f

#define SCAN_B   1024
#define N_SBLK   ((N_NODES + SCAN_B - 1) / SCAN_B)   // 98

// -------- scratch (device globals; no allocation allowed) --------
__device__ __half g_hsh[N_NODES * HID];  // dinv-scaled GEMM output, fp16 (gather buffer)
__device__ float  g_x0 [N_NODES * HID];  // layer-1 output
__device__ float  g_x1 [N_NODES * HID];  // layer-2 output
__device__ int    g_deg   [N_NODES];     // real in-degree (no self loop)
__device__ float  g_dinv  [N_NODES];
__device__ int    g_part  [N_NODES];
__device__ int    g_bsum  [N_SBLK];
__device__ int    g_boff  [N_SBLK];
__device__ int    g_start [N_NODES];     // CSR row offsets (by col/target)
__device__ int    g_cursor[N_NODES];
__device__ int    g_csr   [N_EDGES];     // source node per CSR slot
__device__ int    g_is64;

// -------- edge_index dtype detection (int64 vs int32) --------
__global__ void detect_dtype(const unsigned* __restrict__ ei_raw) {
    if (blockIdx.x == 0 && threadIdx.x == 0) {
        int ok = 1;
        #pragma unroll 1
        for (int i = 0; i < 64; i++)
            if (ei_raw[2 * i + 1] != 0u) ok = 0;
        g_is64 = ok;
    }
}

__device__ __forceinline__ int edge_at(const void* ei, long long idx, int is64) {
    if (is64) return (int)((const long long*)ei)[idx];
    return ((const int*)ei)[idx];
}

// -------- degree --------
__global__ void deg_zero() {
    int v = blockIdx.x * blockDim.x + threadIdx.x;
    if (v < N_NODES) g_deg[v] = 0;
}

__global__ void deg_count(const void* __restrict__ ei) {
    int e = blockIdx.x * blockDim.x + threadIdx.x;
    if (e < N_EDGES) {
        int is64 = g_is64;
        int col = edge_at(ei, (long long)N_EDGES + e, is64);
        atomicAdd(&g_deg[col], 1);
    }
}

// -------- exclusive scan of g_deg (3 kernels) --------
__global__ void scan1() {
    __shared__ int s[SCAN_B];
    int t = threadIdx.x;
    int g = blockIdx.x * SCAN_B + t;
    int v = (g < N_NODES) ? g_deg[g] : 0;
    s[t] = v;
    __syncthreads();
    #pragma unroll
    for (int off = 1; off < SCAN_B; off <<= 1) {
        int x = (t >= off) ? s[t - off] : 0;
        __syncthreads();
        s[t] += x;
        __syncthreads();
    }
    int incl = s[t];
    if (g < N_NODES) g_part[g] = incl - v;
    if (t == SCAN_B - 1) g_bsum[blockIdx.x] = incl;
}

__global__ void scan2() {
    __shared__ int s[128];
    int t = threadIdx.x;
    int v = (t < N_SBLK) ? g_bsum[t] : 0;
    s[t] = v;
    __syncthreads();
    #pragma unroll
    for (int off = 1; off < 128; off <<= 1) {
        int x = (t >= off) ? s[t - off] : 0;
        __syncthreads();
        s[t] += x;
        __syncthreads();
    }
    if (t < N_SBLK) g_boff[t] = s[t] - v;
}

__global__ void scan3() {
    int v = blockIdx.x * blockDim.x + threadIdx.x;
    if (v < N_NODES) {
        int st = g_part[v] + g_boff[v >> 10];
        g_start[v]  = st;
        g_cursor[v] = st;
        g_dinv[v]   = rsqrtf((float)(g_deg[v] + 1));
    }
}

// -------- CSR fill --------
__global__ void csr_fill(const void* __restrict__ ei) {
    int e = blockIdx.x * blockDim.x + threadIdx.x;
    if (e < N_EDGES) {
        int is64 = g_is64;
        int row = edge_at(ei, e, is64);
        int col = edge_at(ei, (long long)N_EDGES + e, is64);
        int pos = atomicAdd(&g_cursor[col], 1);
        g_csr[pos] = row;
    }
}

// -------- GEMM: hsh[v,:] = fp16( dinv[v] * (x[v,:] @ W) ) --------
// sel: 0 -> xext (harness input), 1 -> g_x0, 2 -> g_x1
template <int K>
__global__ void gemm_scale(const float* __restrict__ xext, int sel,
                           const float* __restrict__ W) {
    __shared__ __align__(16) float Wsh[K * HID];
    for (int i = threadIdx.x; i < K * HID; i += blockDim.x) Wsh[i] = W[i];
    __syncthreads();

    int v = blockIdx.x * blockDim.x + threadIdx.x;
    if (v >= N_NODES) return;

    const float* x = (sel == 0) ? xext : (sel == 1 ? g_x0 : g_x1);

    float4 acc[16];
    #pragma unroll
    for (int j = 0; j < 16; j++) acc[j] = make_float4(0.f, 0.f, 0.f, 0.f);

    const float* xr = x + v * K;
    #pragma unroll 4
    for (int k = 0; k < K; k++) {
        float xv = xr[k];
        const float4* wr = (const float4*)(Wsh + k * HID);
        #pragma unroll
        for (int j = 0; j < 16; j++) {
            float4 w = wr[j];
            acc[j].x += xv * w.x;
            acc[j].y += xv * w.y;
            acc[j].z += xv * w.z;
            acc[j].w += xv * w.w;
        }
    }

    float d = g_dinv[v];
    __half2* out = (__half2*)(g_hsh + (v << 6));
    #pragma unroll
    for (int j = 0; j < 16; j++) {
        float4 a = acc[j];
        out[2 * j]     = __floats2half2_rn(a.x * d, a.y * d);
        out[2 * j + 1] = __floats2half2_rn(a.z * d, a.w * d);
    }
}

// -------- fused aggregate + epilogue (fp16 gathers, fp32 accumulate) --------
// 8 threads per node, each owns 8 contiguous features (one 16B fp16 chunk).
// o = relu(BN(dinv[v]*(sum_{src} hs[src] + hs[v]) + b)) (+ residual)
// osel: 0 -> g_x0, 1 -> g_x1, 2 -> dout ; rsel: -1 none, 0 g_x0, 1 g_x1
__device__ __forceinline__ void acc8(float* a, uint4 v) {
    const __half2* h = (const __half2*)&v;
    #pragma unroll
    for (int k = 0; k < 4; k++) {
        float2 f = __half22float2(h[k]);
        a[2 * k]     += f.x;
        a[2 * k + 1] += f.y;
    }
}

__global__ void aggregate_ep(int osel, int rsel, float* __restrict__ dout,
                             const float* __restrict__ b,
                             const float* __restrict__ gamma,
                             const float* __restrict__ beta,
                             const float* __restrict__ mean,
                             const float* __restrict__ var) {
    int t = threadIdx.x;
    int v = blockIdx.x * 32 + (t >> 3);
    int c = t & 7;                     // chunk: 8 halves = 16B
    if (v >= N_NODES) return;

    int start = g_start[v];
    int deg   = g_deg[v];

    // row stride in uint4 units: 64 halves = 8 uint4
    const uint4* __restrict__ hbase = (const uint4*)g_hsh;
    const int*   __restrict__ cs    = g_csr + start;

    float acc[8];
    #pragma unroll
    for (int k = 0; k < 8; k++) acc[k] = 0.f;

    int i = 0;
    for (; i + 4 <= deg; i += 4) {
        int s0 = cs[i], s1 = cs[i + 1], s2 = cs[i + 2], s3 = cs[i + 3];
        uint4 v0 = hbase[(s0 << 3) + c];
        uint4 v1 = hbase[(s1 << 3) + c];
        uint4 v2 = hbase[(s2 << 3) + c];
        uint4 v3 = hbase[(s3 << 3) + c];
        acc8(acc, v0); acc8(acc, v1); acc8(acc, v2); acc8(acc, v3);
    }
    for (; i < deg; i++) {
        uint4 v0 = hbase[(cs[i] << 3) + c];
        acc8(acc, v0);
    }
    // self loop
    acc8(acc, hbase[(v << 3) + c]);

    float d = g_dinv[v];
    int j = c << 3;                    // feature offset (floats)

    float o[8];
    #pragma unroll
    for (int k = 0; k < 8; k++) {
        float bn = (d * acc[k] + b[j + k] - mean[j + k]) *
                   gamma[j + k] * rsqrtf(var[j + k] + BN_EPS) + beta[j + k];
        o[k] = fmaxf(bn, 0.f);
    }

    if (rsel >= 0) {
        const float* r = (rsel == 0) ? g_x0 : g_x1;
        const float4 r0 = *(const float4*)(r + (v << 6) + j);
        const float4 r1 = *(const float4*)(r + (v << 6) + j + 4);
        o[0] += r0.x; o[1] += r0.y; o[2] += r0.z; o[3] += r0.w;
        o[4] += r1.x; o[5] += r1.y; o[6] += r1.z; o[7] += r1.w;
    }

    float* outp = (osel == 0) ? g_x0 : (osel == 1 ? g_x1 : dout);
    float4* op = (float4*)(outp + (v << 6) + j);
    op[0] = make_float4(o[0], o[1], o[2], o[3]);
    op[1] = make_float4(o[4], o[5], o[6], o[7]);
}

// -------- launch --------
extern "C" void kernel_launch(void* const* d_in, const int* in_sizes, int n_in,
                              void* d_out, int out_size) {
    const float* x     = (const float*)d_in[0];
    const void*  ei    = d_in[1];
    const float* W1    = (const float*)d_in[2];
    const float* W2    = (const float*)d_in[3];
    const float* W3    = (const float*)d_in[4];
    const float* b     = (const float*)d_in[5];
    const float* gamma = (const float*)d_in[6];
    const float* beta  = (const float*)d_in[7];
    const float* mean  = (const float*)d_in[8];
    const float* var   = (const float*)d_in[9];
    float* out = (float*)d_out;

    const int T = 256;
    const int gN = (N_NODES + T - 1) / T;
    const int gE = (N_EDGES + T - 1) / T;
    const int gA = (N_NODES + 31) / 32;   // aggregate: 32 nodes/block of 256

    // ---- preprocessing (reused by all 3 layers) ----
    detect_dtype<<<1, 32>>>((const unsigned*)ei);
    deg_zero<<<gN, T>>>();
    deg_count<<<gE, T>>>(ei);
    scan1<<<N_SBLK, SCAN_B>>>();
    scan2<<<1, 128>>>();
    scan3<<<gN, T>>>();
    csr_fill<<<gE, T>>>(ei);

    // layer 1: x(37) -> x0, no residual
    gemm_scale<IN_DIM><<<gN, T>>>(x, 0, W1);
    aggregate_ep<<<gA, T>>>(0, -1, out, b, gamma, beta, mean, var);

    // layer 2: x0 -> x1, residual x0
    gemm_scale<HID><<<gN, T>>>(nullptr, 1, W2);
    aggregate_ep<<<gA, T>>>(1, 0, out, b + HID, gamma + HID, beta + HID,
                            mean + HID, var + HID);

    // layer 3: x1 -> d_out, residual x1
    gemm_scale<HID><<<gN, T>>>(nullptr, 2, W3);
    aggregate_ep<<<gA, T>>>(2, 1, out, b + 2 * HID, gamma + 2 * HID, beta + 2 * HID,
                            mean + 2 * HID, var + 2 * HID);
}

// round 10
// speedup vs baseline: 1.4423x; 1.0272x over previous
#include <cuda_runtime.h>
#include <cuda_fp16.h>

#define N_NODES 100000
#define N_EDGES 1000000
#define IN_DIM  37
#define HID     64
#define BN_EPS  1e-5f

#define SCAN_B   1024
#define N_SBLK   ((N_NODES + SCAN_B - 1) / SCAN_B)   // 98

// -------- scratch (device globals; no allocation allowed) --------
__device__ __half g_hsh[N_NODES * HID];  // dinv-scaled GEMM output, fp16 (gather buffer)
__device__ float  g_x0 [N_NODES * HID];  // layer-1 output
__device__ float  g_x1 [N_NODES * HID];  // layer-2 output
__device__ int    g_deg   [N_NODES];     // real in-degree (no self loop)
__device__ float  g_dinv  [N_NODES];
__device__ int    g_part  [N_NODES];
__device__ int    g_bsum  [N_SBLK];
__device__ int    g_boff  [N_SBLK];
__device__ int    g_start [N_NODES];     // CSR row offsets (by col/target)
__device__ int    g_cursor[N_NODES];
__device__ int    g_csr   [N_EDGES];     // source node per CSR slot
__device__ float  g_s3[3 * HID];         // folded BN scale
__device__ float  g_t3[3 * HID];         // folded BN shift
__device__ int    g_is64;

// -------- edge_index dtype detection (int64 vs int32) --------
__global__ void detect_dtype(const unsigned* __restrict__ ei_raw) {
    if (blockIdx.x == 0 && threadIdx.x == 0) {
        int ok = 1;
        #pragma unroll 1
        for (int i = 0; i < 64; i++)
            if (ei_raw[2 * i + 1] != 0u) ok = 0;
        g_is64 = ok;
    }
}

__device__ __forceinline__ int edge_at(const void* ei, long long idx, int is64) {
    if (is64) return (int)((const long long*)ei)[idx];
    return ((const int*)ei)[idx];
}

// -------- degree --------
__global__ void deg_zero() {
    int v = blockIdx.x * blockDim.x + threadIdx.x;
    if (v < N_NODES) g_deg[v] = 0;
}

__global__ void deg_count(const void* __restrict__ ei) {
    int e = blockIdx.x * blockDim.x + threadIdx.x;
    if (e < N_EDGES) {
        int is64 = g_is64;
        int col = edge_at(ei, (long long)N_EDGES + e, is64);
        atomicAdd(&g_deg[col], 1);
    }
}

// -------- exclusive scan of g_deg (3 kernels) --------
__global__ void scan1() {
    __shared__ int s[SCAN_B];
    int t = threadIdx.x;
    int g = blockIdx.x * SCAN_B + t;
    int v = (g < N_NODES) ? g_deg[g] : 0;
    s[t] = v;
    __syncthreads();
    #pragma unroll
    for (int off = 1; off < SCAN_B; off <<= 1) {
        int x = (t >= off) ? s[t - off] : 0;
        __syncthreads();
        s[t] += x;
        __syncthreads();
    }
    int incl = s[t];
    if (g < N_NODES) g_part[g] = incl - v;
    if (t == SCAN_B - 1) g_bsum[blockIdx.x] = incl;
}

__global__ void scan2() {
    __shared__ int s[128];
    int t = threadIdx.x;
    int v = (t < N_SBLK) ? g_bsum[t] : 0;
    s[t] = v;
    __syncthreads();
    #pragma unroll
    for (int off = 1; off < 128; off <<= 1) {
        int x = (t >= off) ? s[t - off] : 0;
        __syncthreads();
        s[t] += x;
        __syncthreads();
    }
    if (t < N_SBLK) g_boff[t] = s[t] - v;
}

__global__ void scan3() {
    int v = blockIdx.x * blockDim.x + threadIdx.x;
    if (v < N_NODES) {
        int st = g_part[v] + g_boff[v >> 10];
        g_start[v]  = st;
        g_cursor[v] = st;
        g_dinv[v]   = rsqrtf((float)(g_deg[v] + 1));
    }
}

// -------- CSR fill --------
__global__ void csr_fill(const void* __restrict__ ei) {
    int e = blockIdx.x * blockDim.x + threadIdx.x;
    if (e < N_EDGES) {
        int is64 = g_is64;
        int row = edge_at(ei, e, is64);
        int col = edge_at(ei, (long long)N_EDGES + e, is64);
        int pos = atomicAdd(&g_cursor[col], 1);
        g_csr[pos] = row;
    }
}

// -------- fold BN into per-feature scale/shift --------
__global__ void bn_fold(const float* __restrict__ b,
                        const float* __restrict__ gamma,
                        const float* __restrict__ beta,
                        const float* __restrict__ mean,
                        const float* __restrict__ var) {
    int i = threadIdx.x;
    if (i < 3 * HID) {
        float s = gamma[i] * rsqrtf(var[i] + BN_EPS);
        g_s3[i] = s;
        g_t3[i] = (b[i] - mean[i]) * s + beta[i];
    }
}

// -------- GEMM: hsh[v,:] = fp16( dinv[v] * (x[v,:] @ W) ) --------
// sel: 0 -> xext (harness input), 1 -> g_x0, 2 -> g_x1
template <int K>
__global__ void gemm_scale(const float* __restrict__ xext, int sel,
                           const float* __restrict__ W) {
    __shared__ __align__(16) float Wsh[K * HID];
    for (int i = threadIdx.x; i < K * HID; i += blockDim.x) Wsh[i] = W[i];
    __syncthreads();

    int v = blockIdx.x * blockDim.x + threadIdx.x;
    if (v >= N_NODES) return;

    const float* x = (sel == 0) ? xext : (sel == 1 ? g_x0 : g_x1);

    float4 acc[16];
    #pragma unroll
    for (int j = 0; j < 16; j++) acc[j] = make_float4(0.f, 0.f, 0.f, 0.f);

    const float* xr = x + v * K;
    #pragma unroll 4
    for (int k = 0; k < K; k++) {
        float xv = xr[k];
        const float4* wr = (const float4*)(Wsh + k * HID);
        #pragma unroll
        for (int j = 0; j < 16; j++) {
            float4 w = wr[j];
            acc[j].x += xv * w.x;
            acc[j].y += xv * w.y;
            acc[j].z += xv * w.z;
            acc[j].w += xv * w.w;
        }
    }

    float d = g_dinv[v];
    uint4* out = (uint4*)(g_hsh + (v << 6));
    #pragma unroll
    for (int j = 0; j < 8; j++) {
        float4 a0 = acc[2 * j];
        float4 a1 = acc[2 * j + 1];
        __half2 h0 = __floats2half2_rn(a0.x * d, a0.y * d);
        __half2 h1 = __floats2half2_rn(a0.z * d, a0.w * d);
        __half2 h2 = __floats2half2_rn(a1.x * d, a1.y * d);
        __half2 h3 = __floats2half2_rn(a1.z * d, a1.w * d);
        uint4 pk;
        pk.x = *(unsigned*)&h0;
        pk.y = *(unsigned*)&h1;
        pk.z = *(unsigned*)&h2;
        pk.w = *(unsigned*)&h3;
        out[j] = pk;
    }
}

// -------- fused aggregate + epilogue: warp-per-node --------
// lane = (sub = lane>>3 in 0..3, c = lane&7). sub picks edge sub-list, c picks
// the 16B fp16 feature chunk. Butterfly-reduce over sub, lanes sub==0 store.
// o = relu(scale * dinv[v]*(sum hs[src] + hs[v]) + shift) (+ residual)
// osel: 0 -> g_x0, 1 -> g_x1, 2 -> dout ; rsel: -1 none, 0 g_x0, 1 g_x1
// lsel: layer index into g_s3/g_t3 (device globals must be read device-side!)
__device__ __forceinline__ void acc8(float* a, uint4 v) {
    const __half2* h = (const __half2*)&v;
    #pragma unroll
    for (int k = 0; k < 4; k++) {
        float2 f = __half22float2(h[k]);
        a[2 * k]     += f.x;
        a[2 * k + 1] += f.y;
    }
}

__global__ void aggregate_ep(int osel, int rsel, int lsel,
                             float* __restrict__ dout) {
    int lane = threadIdx.x & 31;
    int warp = threadIdx.x >> 5;
    int v = blockIdx.x * 8 + warp;         // 256 threads = 8 warps = 8 nodes
    if (v >= N_NODES) return;

    int c   = lane & 7;
    int sub = lane >> 3;

    int start = g_start[v];
    int deg   = g_deg[v];

    const uint4* __restrict__ hbase = (const uint4*)g_hsh;
    const int*   __restrict__ cs    = g_csr + start;

    float acc[8];
    #pragma unroll
    for (int k = 0; k < 8; k++) acc[k] = 0.f;

    // self loop handled once by sub-list 0
    if (sub == 0) acc8(acc, hbase[(v << 3) + c]);

    // 4-way interleaved edge sub-lists, unroll 2 -> ~8 gathers in flight/warp
    int i = sub;
    for (; i + 4 < deg; i += 8) {
        int s0 = __ldg(cs + i);
        int s1 = __ldg(cs + i + 4);
        uint4 v0 = hbase[(s0 << 3) + c];
        uint4 v1 = hbase[(s1 << 3) + c];
        acc8(acc, v0);
        acc8(acc, v1);
    }
    if (i < deg) {
        uint4 v0 = hbase[(__ldg(cs + i) << 3) + c];
        acc8(acc, v0);
    }

    // reduce over the 4 sub-lists (lanes c, c+8, c+16, c+24)
    #pragma unroll
    for (int k = 0; k < 8; k++) {
        acc[k] += __shfl_xor_sync(0xffffffffu, acc[k], 8);
        acc[k] += __shfl_xor_sync(0xffffffffu, acc[k], 16);
    }

    if (sub == 0) {
        const float* s3 = g_s3 + lsel * HID;   // device-side symbol access
        const float* t3 = g_t3 + lsel * HID;
        float d = g_dinv[v];
        int j = c << 3;

        float o[8];
        #pragma unroll
        for (int k = 0; k < 8; k++)
            o[k] = fmaxf(fmaf(d * acc[k], s3[j + k], t3[j + k]), 0.f);

        if (rsel >= 0) {
            const float* r = (rsel == 0) ? g_x0 : g_x1;
            const float4 r0 = *(const float4*)(r + (v << 6) + j);
            const float4 r1 = *(const float4*)(r + (v << 6) + j + 4);
            o[0] += r0.x; o[1] += r0.y; o[2] += r0.z; o[3] += r0.w;
            o[4] += r1.x; o[5] += r1.y; o[6] += r1.z; o[7] += r1.w;
        }

        float* outp = (osel == 0) ? g_x0 : (osel == 1 ? g_x1 : dout);
        float4* op = (float4*)(outp + (v << 6) + j);
        op[0] = make_float4(o[0], o[1], o[2], o[3]);
        op[1] = make_float4(o[4], o[5], o[6], o[7]);
    }
}

// -------- launch --------
extern "C" void kernel_launch(void* const* d_in, const int* in_sizes, int n_in,
                              void* d_out, int out_size) {
    const float* x     = (const float*)d_in[0];
    const void*  ei    = d_in[1];
    const float* W1    = (const float*)d_in[2];
    const float* W2    = (const float*)d_in[3];
    const float* W3    = (const float*)d_in[4];
    const float* b     = (const float*)d_in[5];
    const float* gamma = (const float*)d_in[6];
    const float* beta  = (const float*)d_in[7];
    const float* mean  = (const float*)d_in[8];
    const float* var   = (const float*)d_in[9];
    float* out = (float*)d_out;

    const int T = 256;
    const int gN = (N_NODES + T - 1) / T;
    const int gE = (N_EDGES + T - 1) / T;
    const int gA = (N_NODES + 7) / 8;     // aggregate: 8 nodes/block (warp/node)

    // ---- preprocessing (reused by all 3 layers) ----
    detect_dtype<<<1, 32>>>((const unsigned*)ei);
    deg_zero<<<gN, T>>>();
    deg_count<<<gE, T>>>(ei);
    scan1<<<N_SBLK, SCAN_B>>>();
    scan2<<<1, 128>>>();
    scan3<<<gN, T>>>();
    csr_fill<<<gE, T>>>(ei);
    bn_fold<<<1, 3 * HID>>>(b, gamma, beta, mean, var);

    // layer 1: x(37) -> x0, no residual
    gemm_scale<IN_DIM><<<gN, T>>>(x, 0, W1);
    aggregate_ep<<<gA, T>>>(0, -1, 0, out);

    // layer 2: x0 -> x1, residual x0
    gemm_scale<HID><<<gN, T>>>(nullptr, 1, W2);
    aggregate_ep<<<gA, T>>>(1, 0, 1, out);

    // layer 3: x1 -> d_out, residual x1
    gemm_scale<HID><<<gN, T>>>(nullptr, 2, W3);
    aggregate_ep<<<gA, T>>>(2, 1, 2, out);
}